// round 3
// baseline (speedup 1.0000x reference)
#include <cuda_runtime.h>

// ===========================================================================
// QLP_14731737825362: 8-wire VQC forward, B = 16384 samples, DIM = 256.
// One warp per sample; 256 complex amps = 8 complex per lane in registers.
// Index bit mapping: j = lane*8 + r  (lane = bits[7:3], r = bits[2:0]).
// Wire w acts on bit position p = 7 - w.
//   wires 5,6,7 -> p = 2,1,0 : in-register butterflies
//   wires 0..4  -> p = 7..3  : __shfl_xor butterflies, mask = 1 << (4-w)
// Precomputed per launch (setup kernel): CRZ diagonal phase tables (256
// complex each) and cos/sin of shared RY half-angles.
// ===========================================================================

__device__ float2 g_diag1[256];
__device__ float2 g_diag2[256];
__device__ float  g_C1[8], g_S1[8], g_C2[8], g_S2[8];

__global__ void vqc_setup(const float* __restrict__ ry1, const float* __restrict__ crz1,
                          const float* __restrict__ ry2, const float* __restrict__ crz2) {
    int j = threadIdx.x;  // 0..255 = basis index
    if (j < 8) {
        g_C1[j] = cosf(ry1[j] * 0.5f); g_S1[j] = sinf(ry1[j] * 0.5f);
        g_C2[j] = cosf(ry2[j] * 0.5f); g_S2[j] = sinf(ry2[j] * 0.5f);
    }
    // CRZ block diagonals: expo = sum_w bit_ctrl(j) * (bit_tgt(j) - 0.5) * theta_w
    // block 1: ctrl = w, tgt = (w+1) % 8 ; block 2: ctrl = w, tgt = (w-1) % 8
    // bit of wire w in index j is (j >> (7-w)) & 1
    float e1 = 0.f, e2 = 0.f;
    #pragma unroll
    for (int w = 0; w < 8; w++) {
        float bc  = (float)((j >> (7 - w)) & 1);
        float bt1 = (float)((j >> (7 - ((w + 1) & 7))) & 1);
        float bt2 = (float)((j >> (7 - ((w + 7) & 7))) & 1);
        e1 += bc * (bt1 - 0.5f) * crz1[w];
        e2 += bc * (bt2 - 0.5f) * crz2[w];
    }
    g_diag1[j] = make_float2(cosf(e1), sinf(e1));
    g_diag2[j] = make_float2(cosf(e2), sinf(e2));
}

// RY butterfly on one amplitude pair (a = bit 0 side, b = bit 1 side):
//   a' = c*a - s*b ; b' = s*a + c*b    (applied to re and im independently)
__device__ __forceinline__ void ry_pair(float& ar, float& ai, float& br, float& bi,
                                        float c, float s) {
    float nar = fmaf(c, ar, -s * br);
    float nai = fmaf(c, ai, -s * bi);
    float nbr = fmaf(s, ar,  c * br);
    float nbi = fmaf(s, ai,  c * bi);
    ar = nar; ai = nai; br = nbr; bi = nbi;
}

__device__ __forceinline__ void ry_layer(float sr[8], float si[8],
                                         const float* __restrict__ C,
                                         const float* __restrict__ S, int lane) {
    // wire 5 (p=2): pairs (r, r+4)
    {
        float c = C[5], s = S[5];
        #pragma unroll
        for (int r = 0; r < 4; r++) ry_pair(sr[r], si[r], sr[r + 4], si[r + 4], c, s);
    }
    // wire 6 (p=1): pairs (r, r+2) for r in {0,1,4,5}
    {
        float c = C[6], s = S[6];
        #pragma unroll
        for (int r = 0; r < 8; r++)
            if (!(r & 2)) ry_pair(sr[r], si[r], sr[r + 2], si[r + 2], c, s);
    }
    // wire 7 (p=0): pairs (r, r+1) for even r
    {
        float c = C[7], s = S[7];
        #pragma unroll
        for (int r = 0; r < 8; r += 2) ry_pair(sr[r], si[r], sr[r + 1], si[r + 1], c, s);
    }
    // wires 0..4: cross-lane. Lane with bit=0: new = c*mine - s*partner;
    // lane with bit=1: new = c*mine + s*partner.
    #pragma unroll
    for (int w = 0; w < 5; w++) {
        float c = C[w], s = S[w];
        int   mk  = 1 << (4 - w);
        float sgn = ((lane >> (4 - w)) & 1) ? s : -s;
        #pragma unroll
        for (int r = 0; r < 8; r++) {
            float pr = __shfl_xor_sync(0xffffffffu, sr[r], mk);
            float pi = __shfl_xor_sync(0xffffffffu, si[r], mk);
            sr[r] = fmaf(sgn, pr, c * sr[r]);
            si[r] = fmaf(sgn, pi, c * si[r]);
        }
    }
}

__global__ __launch_bounds__(256, 8) void vqc_main(const float* __restrict__ x,
                                                   float* __restrict__ out, int nsamp) {
    int gw   = (int)((blockIdx.x * blockDim.x + threadIdx.x) >> 5);
    int lane = threadIdx.x & 31;
    if (gw >= nsamp) return;

    // ---- per-sample encoder half-angle cos/sin ----
    const float* xs = x + (size_t)gw * 8;
    float ce[8], se[8];
    #pragma unroll
    for (int w = 0; w < 8; w++) __sincosf(xs[w] * 0.5f, &se[w], &ce[w]);

    // ---- product state after encoding: amp[j] = prod_w (bit ? s : c), real ----
    float base = 1.0f;
    #pragma unroll
    for (int w = 0; w < 5; w++)
        base *= ((lane >> (4 - w)) & 1) ? se[w] : ce[w];

    float sr[8], si[8];
    #pragma unroll
    for (int r = 0; r < 8; r++) {
        float v = base;
        v *= (r & 4) ? se[5] : ce[5];
        v *= (r & 2) ? se[6] : ce[6];
        v *= (r & 1) ? se[7] : ce[7];
        // fold in diag1 (state still real here: complex mul degenerates)
        float2 d = g_diag1[lane * 8 + r];
        sr[r] = v * d.x;
        si[r] = v * d.y;
    }

    // ---- RY layer 1 (shared params) ----
    ry_layer(sr, si, g_C1, g_S1, lane);

    // ---- diag2 (full complex multiply) ----
    #pragma unroll
    for (int r = 0; r < 8; r++) {
        float2 d = g_diag2[lane * 8 + r];
        float re = fmaf(sr[r], d.x, -si[r] * d.y);
        float im = fmaf(sr[r], d.y,  si[r] * d.x);
        sr[r] = re; si[r] = im;
    }

    // ---- RY layer 2 ----
    ry_layer(sr, si, g_C2, g_S2, lane);

    // ---- Z expectations: out[w] = sum_j |amp_j|^2 * (1 - 2*bit_w(j)) ----
    // Wires 0..4: sign depends only on lane -> factor through P = sum_r p[r].
    // Wires 5..7: sign depends only on r (compile-time).
    float P = 0.f, a5 = 0.f, a6 = 0.f, a7 = 0.f;
    #pragma unroll
    for (int r = 0; r < 8; r++) {
        float p = fmaf(sr[r], sr[r], si[r] * si[r]);
        P  += p;
        a5 += (r & 4) ? -p : p;
        a6 += (r & 2) ? -p : p;
        a7 += (r & 1) ? -p : p;
    }
    float acc[8];
    #pragma unroll
    for (int w = 0; w < 5; w++)
        acc[w] = ((lane >> (4 - w)) & 1) ? -P : P;
    acc[5] = a5; acc[6] = a6; acc[7] = a7;

    #pragma unroll
    for (int m = 16; m >= 1; m >>= 1) {
        #pragma unroll
        for (int w = 0; w < 8; w++)
            acc[w] += __shfl_xor_sync(0xffffffffu, acc[w], m);
    }

    if (lane == 0) {
        float4* o = (float4*)(out + (size_t)gw * 8);
        o[0] = make_float4(acc[0], acc[1], acc[2], acc[3]);
        o[1] = make_float4(acc[4], acc[5], acc[6], acc[7]);
    }
}

extern "C" void kernel_launch(void* const* d_in, const int* in_sizes, int n_in,
                              void* d_out, int out_size) {
    const float* x    = (const float*)d_in[0];
    const float* ry1  = (const float*)d_in[1];
    const float* crz1 = (const float*)d_in[2];
    const float* ry2  = (const float*)d_in[3];
    const float* crz2 = (const float*)d_in[4];
    float* out = (float*)d_out;

    int nsamp = in_sizes[0] / 8;  // 16384

    vqc_setup<<<1, 256>>>(ry1, crz1, ry2, crz2);

    const int warps_per_block = 8;           // 256 threads
    int blocks = (nsamp + warps_per_block - 1) / warps_per_block;
    vqc_main<<<blocks, 256>>>(x, out, nsamp);
}

// round 5
// speedup vs baseline: 1.4779x; 1.4779x over previous
#include <cuda_runtime.h>

// ===========================================================================
// QLP_14731737825362: 8-wire VQC, B = 16384, DIM = 256. One warp per sample,
// 8 complex amps per lane.
//
// Layout A: j = lane*8 + r ; lane bits L4..L0 = wires 0..4, reg bits = wires 5,6,7.
// Layout B: lane bits = wires 0,1,4?? -> precisely: lane' = (L&24)|r_old,
//           reg' = L&7  (swap lane[2:0] <-> reg[2:0]); reg bits = wires 2,3,4.
// Each RY layer: 3 wires in-register, 2 wires via shfl, 3 wires in-register
// after a conflict-free smem transpose (stride-9 padding).
// Diag tables stored coalesced (r-major); diag2 pre-permuted for layout B.
// ===========================================================================

__device__ float2 g_d1T[256];   // [r*32 + lane]   (layout A, r-major)
__device__ float2 g_d2BT[256];  // [r'*32 + lane'] (layout B, r-major)
__device__ float  g_C1[8], g_S1[8], g_C2[8], g_S2[8];

__global__ void vqc_setup(const float* __restrict__ ry1, const float* __restrict__ crz1,
                          const float* __restrict__ ry2, const float* __restrict__ crz2) {
    int j = threadIdx.x;  // 0..255 basis index
    if (j < 8) {
        g_C1[j] = cosf(ry1[j] * 0.5f); g_S1[j] = sinf(ry1[j] * 0.5f);
        g_C2[j] = cosf(ry2[j] * 0.5f); g_S2[j] = sinf(ry2[j] * 0.5f);
    }
    float e1 = 0.f, e2 = 0.f;
    #pragma unroll
    for (int w = 0; w < 8; w++) {
        float bc  = (float)((j >> (7 - w)) & 1);
        float bt1 = (float)((j >> (7 - ((w + 1) & 7))) & 1);
        float bt2 = (float)((j >> (7 - ((w + 7) & 7))) & 1);
        e1 += bc * (bt1 - 0.5f) * crz1[w];
        e2 += bc * (bt2 - 0.5f) * crz2[w];
    }
    // diag1 in layout A, r-major: value (lane=j>>3, r=j&7)
    g_d1T[(j & 7) * 32 + (j >> 3)] = make_float2(cosf(e1), sinf(e1));
    // diag2 in layout B, r-major: lane' = (Lo&24)|ro, r' = Lo&7 with Lo=j>>3, ro=j&7
    int Lp = ((j >> 3) & 24) | (j & 7);
    int rp = (j >> 3) & 7;
    g_d2BT[rp * 32 + Lp] = make_float2(cosf(e2), sinf(e2));
}

__device__ __forceinline__ void ry_pair(float& ar, float& ai, float& br, float& bi,
                                        float c, float s) {
    float nar = fmaf(c, ar, -s * br);
    float nai = fmaf(c, ai, -s * bi);
    float nbr = fmaf(s, ar,  c * br);
    float nbi = fmaf(s, ai,  c * bi);
    ar = nar; ai = nai; br = nbr; bi = nbi;
}

__device__ __forceinline__ void ry_reg(float sr[8], float si[8], float c, float s, int stride) {
    #pragma unroll
    for (int r = 0; r < 8; r++)
        if (!(r & stride))
            ry_pair(sr[r], si[r], sr[r + stride], si[r + stride], c, s);
}

__device__ __forceinline__ void ry_cross(float sr[8], float si[8], float c, float s,
                                         int mask, int lane) {
    float sgn = (lane & mask) ? s : -s;
    #pragma unroll
    for (int r = 0; r < 8; r++) {
        float pr = __shfl_xor_sync(0xffffffffu, sr[r], mask);
        float pi = __shfl_xor_sync(0xffffffffu, si[r], mask);
        sr[r] = fmaf(sgn, pr, c * sr[r]);
        si[r] = fmaf(sgn, pi, c * si[r]);
    }
}

// Exchange lane bits [2:0] with reg bits [2:0] via smem (involution).
// Stride-9 padding: store addr = 9*lane + r (9L mod 32 hits all banks);
// load addr = 9*((lane&24)+r) + (lane&7) — also conflict-free.
__device__ __forceinline__ void transpose_swap3(float sr[8], float si[8],
                                                float* __restrict__ bre,
                                                float* __restrict__ bim, int lane) {
    __syncwarp();
    #pragma unroll
    for (int r = 0; r < 8; r++) {
        bre[9 * lane + r] = sr[r];
        bim[9 * lane + r] = si[r];
    }
    __syncwarp();
    int base = 9 * (lane & 24) + (lane & 7);
    #pragma unroll
    for (int r = 0; r < 8; r++) {
        int a = base + 9 * r;
        sr[r] = bre[a];
        si[r] = bim[a];
    }
}

__global__ __launch_bounds__(256) void vqc_main(const float* __restrict__ x,
                                                float* __restrict__ out, int nsamp) {
    __shared__ float trbuf[2][8][288];   // 9*32 floats per warp, re/im
    int gw   = (int)((blockIdx.x * blockDim.x + threadIdx.x) >> 5);
    int lane = threadIdx.x & 31;
    int wi   = (threadIdx.x >> 5) & 7;
    if (gw >= nsamp) return;
    float* bre = trbuf[0][wi];
    float* bim = trbuf[1][wi];

    // ---- shared RY params via vector loads (uniform, L1-hit) ----
    float C1[8], S1[8], C2[8], S2[8];
    {
        float4 a0 = ((const float4*)g_C1)[0], a1 = ((const float4*)g_C1)[1];
        float4 b0 = ((const float4*)g_S1)[0], b1 = ((const float4*)g_S1)[1];
        float4 c0 = ((const float4*)g_C2)[0], c1 = ((const float4*)g_C2)[1];
        float4 d0 = ((const float4*)g_S2)[0], d1 = ((const float4*)g_S2)[1];
        C1[0]=a0.x;C1[1]=a0.y;C1[2]=a0.z;C1[3]=a0.w;C1[4]=a1.x;C1[5]=a1.y;C1[6]=a1.z;C1[7]=a1.w;
        S1[0]=b0.x;S1[1]=b0.y;S1[2]=b0.z;S1[3]=b0.w;S1[4]=b1.x;S1[5]=b1.y;S1[6]=b1.z;S1[7]=b1.w;
        C2[0]=c0.x;C2[1]=c0.y;C2[2]=c0.z;C2[3]=c0.w;C2[4]=c1.x;C2[5]=c1.y;C2[6]=c1.z;C2[7]=c1.w;
        S2[0]=d0.x;S2[1]=d0.y;S2[2]=d0.z;S2[3]=d0.w;S2[4]=d1.x;S2[5]=d1.y;S2[6]=d1.z;S2[7]=d1.w;
    }

    // ---- per-sample encoder half-angle cos/sin ----
    const float* xs = x + (size_t)gw * 8;
    float ce[8], se[8];
    #pragma unroll
    for (int w = 0; w < 8; w++) __sincosf(xs[w] * 0.5f, &se[w], &ce[w]);

    // ---- product state (layout A), fold diag1 ----
    float base = 1.0f;
    #pragma unroll
    for (int w = 0; w < 5; w++)
        base *= ((lane >> (4 - w)) & 1) ? se[w] : ce[w];

    float sr[8], si[8];
    #pragma unroll
    for (int r = 0; r < 8; r++) {
        float v = base;
        v *= (r & 4) ? se[5] : ce[5];
        v *= (r & 2) ? se[6] : ce[6];
        v *= (r & 1) ? se[7] : ce[7];
        float2 d = g_d1T[r * 32 + lane];     // coalesced
        sr[r] = v * d.x;
        si[r] = v * d.y;
    }

    // ---- RY layer 1 ----
    ry_reg(sr, si, C1[5], S1[5], 4);         // layout A reg wires 5,6,7
    ry_reg(sr, si, C1[6], S1[6], 2);
    ry_reg(sr, si, C1[7], S1[7], 1);
    ry_cross(sr, si, C1[0], S1[0], 16, lane);
    ry_cross(sr, si, C1[1], S1[1],  8, lane);
    transpose_swap3(sr, si, bre, bim, lane); // A -> B
    ry_reg(sr, si, C1[2], S1[2], 4);         // layout B reg wires 2,3,4
    ry_reg(sr, si, C1[3], S1[3], 2);
    ry_reg(sr, si, C1[4], S1[4], 1);

    // ---- diag2 (layout B, coalesced, full complex multiply) ----
    #pragma unroll
    for (int r = 0; r < 8; r++) {
        float2 d = g_d2BT[r * 32 + lane];
        float re = fmaf(sr[r], d.x, -si[r] * d.y);
        float im = fmaf(sr[r], d.y,  si[r] * d.x);
        sr[r] = re; si[r] = im;
    }

    // ---- RY layer 2 ----
    ry_reg(sr, si, C2[2], S2[2], 4);
    ry_reg(sr, si, C2[3], S2[3], 2);
    ry_reg(sr, si, C2[4], S2[4], 1);
    ry_cross(sr, si, C2[0], S2[0], 16, lane);
    ry_cross(sr, si, C2[1], S2[1],  8, lane);
    transpose_swap3(sr, si, bre, bim, lane); // B -> A
    ry_reg(sr, si, C2[5], S2[5], 4);
    ry_reg(sr, si, C2[6], S2[6], 2);
    ry_reg(sr, si, C2[7], S2[7], 1);

    // ---- probs & reduction (layout A) ----
    float P = 0.f, a5 = 0.f, a6 = 0.f, a7 = 0.f;
    #pragma unroll
    for (int r = 0; r < 8; r++) {
        float p = fmaf(sr[r], sr[r], si[r] * si[r]);
        P  += p;
        a5 += (r & 4) ? -p : p;
        a6 += (r & 2) ? -p : p;
        a7 += (r & 1) ? -p : p;
    }
    // progressive Walsh over lanes: d_b = sum_lane (1-2*bit_b(lane)) * P
    const unsigned F = 0xffffffffu;
    float s = P;
    float d0, d1, d2, d3, d4;
    {   // m = 1
        float t = __shfl_xor_sync(F, s, 1);
        d0 = (lane & 1) ? (t - s) : (s - t); s += t;
        a5 += __shfl_xor_sync(F, a5, 1);
        a6 += __shfl_xor_sync(F, a6, 1);
        a7 += __shfl_xor_sync(F, a7, 1);
    }
    {   // m = 2
        float t = __shfl_xor_sync(F, s, 2);
        d1 = (lane & 2) ? (t - s) : (s - t); s += t;
        d0 += __shfl_xor_sync(F, d0, 2);
        a5 += __shfl_xor_sync(F, a5, 2);
        a6 += __shfl_xor_sync(F, a6, 2);
        a7 += __shfl_xor_sync(F, a7, 2);
    }
    {   // m = 4
        float t = __shfl_xor_sync(F, s, 4);
        d2 = (lane & 4) ? (t - s) : (s - t); s += t;
        d0 += __shfl_xor_sync(F, d0, 4);
        d1 += __shfl_xor_sync(F, d1, 4);
        a5 += __shfl_xor_sync(F, a5, 4);
        a6 += __shfl_xor_sync(F, a6, 4);
        a7 += __shfl_xor_sync(F, a7, 4);
    }
    {   // m = 8
        float t = __shfl_xor_sync(F, s, 8);
        d3 = (lane & 8) ? (t - s) : (s - t); s += t;
        d0 += __shfl_xor_sync(F, d0, 8);
        d1 += __shfl_xor_sync(F, d1, 8);
        d2 += __shfl_xor_sync(F, d2, 8);
        a5 += __shfl_xor_sync(F, a5, 8);
        a6 += __shfl_xor_sync(F, a6, 8);
        a7 += __shfl_xor_sync(F, a7, 8);
    }
    {   // m = 16
        float t = __shfl_xor_sync(F, s, 16);
        d4 = (lane & 16) ? (t - s) : (s - t);
        d0 += __shfl_xor_sync(F, d0, 16);
        d1 += __shfl_xor_sync(F, d1, 16);
        d2 += __shfl_xor_sync(F, d2, 16);
        d3 += __shfl_xor_sync(F, d3, 16);
        a5 += __shfl_xor_sync(F, a5, 16);
        a6 += __shfl_xor_sync(F, a6, 16);
        a7 += __shfl_xor_sync(F, a7, 16);
    }
    // wire w uses lane bit (4-w): out[0]=d4, out[1]=d3, out[2]=d2, out[3]=d1, out[4]=d0
    if (lane == 0) {
        float4* o = (float4*)(out + (size_t)gw * 8);
        o[0] = make_float4(d4, d3, d2, d1);
        o[1] = make_float4(d0, a5, a6, a7);
    }
}

extern "C" void kernel_launch(void* const* d_in, const int* in_sizes, int n_in,
                              void* d_out, int out_size) {
    const float* x    = (const float*)d_in[0];
    const float* ry1  = (const float*)d_in[1];
    const float* crz1 = (const float*)d_in[2];
    const float* ry2  = (const float*)d_in[3];
    const float* crz2 = (const float*)d_in[4];
    float* out = (float*)d_out;

    int nsamp = in_sizes[0] / 8;  // 16384

    vqc_setup<<<1, 256>>>(ry1, crz1, ry2, crz2);

    int blocks = (nsamp + 7) / 8;  // 8 warps (256 threads) per block
    vqc_main<<<blocks, 256>>>(x, out, nsamp);
}

// round 7
// speedup vs baseline: 1.5682x; 1.0611x over previous
#include <cuda_runtime.h>

// ===========================================================================
// QLP_14731737825362: 8-wire VQC, B = 16384, DIM = 256. One warp per sample,
// 8 complex amps per lane, each amp PACKED as f32x2 (re=lo, im=hi) so every
// butterfly issues half the FMA-pipe instructions via fma.rn.f32x2 (sm_100+).
//
// Layout A: j = lane*8 + r ; lane bits = wires 0..4, reg bits = wires 5,6,7.
// Layout B (after smem transpose swapping lane[2:0] <-> r): reg = wires 2,3,4.
// Each RY layer: 3 reg wires, 2 shfl wires (0,1), transpose, 3 reg wires.
// ===========================================================================

typedef unsigned long long u64;

__device__ float2 g_d1T[256];   // diag1, layout A, r-major  [r*32 + lane]
__device__ float2 g_d2BT[256];  // diag2, layout B, r-major
__device__ float  g_C1[8], g_S1[8], g_C2[8], g_S2[8];

__global__ void vqc_setup(const float* __restrict__ ry1, const float* __restrict__ crz1,
                          const float* __restrict__ ry2, const float* __restrict__ crz2) {
    int j = threadIdx.x;  // 0..255 basis index
    if (j < 8) {
        g_C1[j] = cosf(ry1[j] * 0.5f); g_S1[j] = sinf(ry1[j] * 0.5f);
        g_C2[j] = cosf(ry2[j] * 0.5f); g_S2[j] = sinf(ry2[j] * 0.5f);
    }
    float e1 = 0.f, e2 = 0.f;
    #pragma unroll
    for (int w = 0; w < 8; w++) {
        float bc  = (float)((j >> (7 - w)) & 1);
        float bt1 = (float)((j >> (7 - ((w + 1) & 7))) & 1);
        float bt2 = (float)((j >> (7 - ((w + 7) & 7))) & 1);
        e1 += bc * (bt1 - 0.5f) * crz1[w];
        e2 += bc * (bt2 - 0.5f) * crz2[w];
    }
    g_d1T[(j & 7) * 32 + (j >> 3)] = make_float2(cosf(e1), sinf(e1));
    int Lp = ((j >> 3) & 24) | (j & 7);
    int rp = (j >> 3) & 7;
    g_d2BT[rp * 32 + Lp] = make_float2(cosf(e2), sinf(e2));
}

// ---- packed f32x2 primitives ----
__device__ __forceinline__ u64 pk2(float lo, float hi) {
    u64 r; asm("mov.b64 %0, {%1, %2};" : "=l"(r) : "f"(lo), "f"(hi)); return r;
}
__device__ __forceinline__ void upk2(float& lo, float& hi, u64 v) {
    asm("mov.b64 {%0, %1}, %2;" : "=f"(lo), "=f"(hi) : "l"(v));
}
__device__ __forceinline__ u64 mul2(u64 a, u64 b) {
    u64 d; asm("mul.rn.f32x2 %0, %1, %2;" : "=l"(d) : "l"(a), "l"(b)); return d;
}
__device__ __forceinline__ u64 add2(u64 a, u64 b) {
    u64 d; asm("add.rn.f32x2 %0, %1, %2;" : "=l"(d) : "l"(a), "l"(b)); return d;
}
__device__ __forceinline__ u64 fma2(u64 a, u64 b, u64 c) {
    u64 d; asm("fma.rn.f32x2 %0, %1, %2, %3;" : "=l"(d) : "l"(a), "l"(b), "l"(c)); return d;
}

// RY butterfly on packed pair: a' = c*a - s*b ; b' = s*a + c*b
__device__ __forceinline__ void ry_pair2(u64& a, u64& b, u64 cc, u64 ss, u64 nss) {
    u64 na = fma2(nss, b, mul2(cc, a));
    u64 nb = fma2(ss,  a, mul2(cc, b));
    a = na; b = nb;
}

__device__ __forceinline__ void ry_reg2(u64 s[8], float c, float sv, int stride) {
    u64 cc = pk2(c, c), ss = pk2(sv, sv), nss = pk2(-sv, -sv);
    #pragma unroll
    for (int r = 0; r < 8; r++)
        if (!(r & stride))
            ry_pair2(s[r], s[r + stride], cc, ss, nss);
}

__device__ __forceinline__ void ry_cross2(u64 s[8], float c, float sv, int mask, int lane) {
    u64 cc = pk2(c, c);
    float sg = (lane & mask) ? sv : -sv;
    u64 sgn = pk2(sg, sg);
    #pragma unroll
    for (int r = 0; r < 8; r++) {
        u64 p = __shfl_xor_sync(0xffffffffu, s[r], mask);
        s[r] = fma2(sgn, p, mul2(cc, s[r]));
    }
}

// Exchange lane bits [2:0] with reg bits [2:0] via smem (involution).
// Stride-9 addressing: both store (9L+r) and load (9((L&24)|r)+(L&7)) are
// distinct mod 16 within each 16-lane phase -> conflict-free for 64-bit ops.
__device__ __forceinline__ void transpose2(u64 s[8], u64* __restrict__ buf, int lane) {
    __syncwarp();
    #pragma unroll
    for (int r = 0; r < 8; r++) buf[9 * lane + r] = s[r];
    __syncwarp();
    int base = 9 * (lane & 24) + (lane & 7);
    #pragma unroll
    for (int r = 0; r < 8; r++) s[r] = buf[base + 9 * r];
}

__device__ __forceinline__ void load8(float* dst, const float* g) {
    float4 a = ((const float4*)g)[0], b = ((const float4*)g)[1];
    dst[0]=a.x; dst[1]=a.y; dst[2]=a.z; dst[3]=a.w;
    dst[4]=b.x; dst[5]=b.y; dst[6]=b.z; dst[7]=b.w;
}

__global__ __launch_bounds__(256) void vqc_main(const float* __restrict__ x,
                                                float* __restrict__ out, int nsamp) {
    __shared__ u64 trbuf[8][288];    // 9*32 packed amps per warp (2304 B/warp)
    int gw   = (int)((blockIdx.x * blockDim.x + threadIdx.x) >> 5);
    int lane = threadIdx.x & 31;
    int wi   = (threadIdx.x >> 5) & 7;
    if (gw >= nsamp) return;
    u64* buf = trbuf[wi];

    // ---- per-sample encoder half-angle cos/sin ----
    const float* xs = x + (size_t)gw * 8;
    float ce[8], se[8];
    #pragma unroll
    for (int w = 0; w < 8; w++) __sincosf(xs[w] * 0.5f, &se[w], &ce[w]);

    // ---- product state (layout A), fold diag1 (state real -> 1 mul2) ----
    float base = 1.0f;
    #pragma unroll
    for (int w = 0; w < 5; w++)
        base *= ((lane >> (4 - w)) & 1) ? se[w] : ce[w];

    float gg[4] = { ce[6]*ce[7], ce[6]*se[7], se[6]*ce[7], se[6]*se[7] };
    float hh[2] = { base*ce[5], base*se[5] };

    const u64* d1 = (const u64*)g_d1T;
    u64 s[8];
    #pragma unroll
    for (int r = 0; r < 8; r++) {
        float v = hh[r >> 2] * gg[r & 3];
        s[r] = mul2(pk2(v, v), d1[r * 32 + lane]);    // (v*cos, v*sin)
    }

    // ---- RY layer 1 ----
    {
        float C[8], S[8];
        load8(C, g_C1); load8(S, g_S1);
        ry_reg2(s, C[5], S[5], 4);          // layout A reg wires 5,6,7
        ry_reg2(s, C[6], S[6], 2);
        ry_reg2(s, C[7], S[7], 1);
        ry_cross2(s, C[0], S[0], 16, lane);
        ry_cross2(s, C[1], S[1],  8, lane);
        transpose2(s, buf, lane);           // A -> B
        ry_reg2(s, C[2], S[2], 4);          // layout B reg wires 2,3,4
        ry_reg2(s, C[3], S[3], 2);
        ry_reg2(s, C[4], S[4], 1);
    }

    // ---- diag2 (layout B, coalesced, full complex multiply) ----
    #pragma unroll
    for (int r = 0; r < 8; r++) {
        float2 d = g_d2BT[r * 32 + lane];
        float re, im; upk2(re, im, s[r]);
        float nr = fmaf(re, d.x, -im * d.y);
        float ni = fmaf(re, d.y,  im * d.x);
        s[r] = pk2(nr, ni);
    }

    // ---- RY layer 2 ----
    {
        float C[8], S[8];
        load8(C, g_C2); load8(S, g_S2);
        ry_reg2(s, C[2], S[2], 4);
        ry_reg2(s, C[3], S[3], 2);
        ry_reg2(s, C[4], S[4], 1);
        ry_cross2(s, C[0], S[0], 16, lane);
        ry_cross2(s, C[1], S[1],  8, lane);
        transpose2(s, buf, lane);           // B -> A
        ry_reg2(s, C[5], S[5], 4);
        ry_reg2(s, C[6], S[6], 2);
        ry_reg2(s, C[7], S[7], 1);
    }

    // ---- probs (packed tree; sub via fma2 with (-1,-1)) ----
    u64 NEG1 = pk2(-1.f, -1.f);
    u64 q0 = mul2(s[0], s[0]), q1 = mul2(s[1], s[1]);
    u64 q2 = mul2(s[2], s[2]), q3 = mul2(s[3], s[3]);
    u64 q4 = mul2(s[4], s[4]), q5 = mul2(s[5], s[5]);
    u64 q6 = mul2(s[6], s[6]), q7 = mul2(s[7], s[7]);
    u64 u0 = add2(q0, q1), u1 = add2(q2, q3), u2 = add2(q4, q5), u3 = add2(q6, q7);
    u64 v0 = add2(u0, u1), v1 = add2(u2, u3);
    u64 Pp  = add2(v0, v1);
    u64 a5p = fma2(v1, NEG1, v0);                                   // v0 - v1
    u64 a6p = add2(fma2(u1, NEG1, u0), fma2(u3, NEG1, u2));
    u64 a7p = add2(add2(fma2(q1, NEG1, q0), fma2(q3, NEG1, q2)),
                   add2(fma2(q5, NEG1, q4), fma2(q7, NEG1, q6)));
    float lo, hi;
    float P , a5, a6, a7;
    upk2(lo, hi, Pp ); P  = lo + hi;
    upk2(lo, hi, a5p); a5 = lo + hi;
    upk2(lo, hi, a6p); a6 = lo + hi;
    upk2(lo, hi, a7p); a7 = lo + hi;

    // ---- progressive Walsh over lanes (wires 0..4) + sums (wires 5..7) ----
    const unsigned F = 0xffffffffu;
    float sP = P;
    float d0, d1s, d2s, d3s, d4s;
    {   // m = 1
        float t = __shfl_xor_sync(F, sP, 1);
        d0 = (lane & 1) ? (t - sP) : (sP - t); sP += t;
        a5 += __shfl_xor_sync(F, a5, 1);
        a6 += __shfl_xor_sync(F, a6, 1);
        a7 += __shfl_xor_sync(F, a7, 1);
    }
    {   // m = 2
        float t = __shfl_xor_sync(F, sP, 2);
        d1s = (lane & 2) ? (t - sP) : (sP - t); sP += t;
        d0 += __shfl_xor_sync(F, d0, 2);
        a5 += __shfl_xor_sync(F, a5, 2);
        a6 += __shfl_xor_sync(F, a6, 2);
        a7 += __shfl_xor_sync(F, a7, 2);
    }
    {   // m = 4
        float t = __shfl_xor_sync(F, sP, 4);
        d2s = (lane & 4) ? (t - sP) : (sP - t); sP += t;
        d0  += __shfl_xor_sync(F, d0, 4);
        d1s += __shfl_xor_sync(F, d1s, 4);
        a5  += __shfl_xor_sync(F, a5, 4);
        a6  += __shfl_xor_sync(F, a6, 4);
        a7  += __shfl_xor_sync(F, a7, 4);
    }
    {   // m = 8
        float t = __shfl_xor_sync(F, sP, 8);
        d3s = (lane & 8) ? (t - sP) : (sP - t); sP += t;
        d0  += __shfl_xor_sync(F, d0, 8);
        d1s += __shfl_xor_sync(F, d1s, 8);
        d2s += __shfl_xor_sync(F, d2s, 8);
        a5  += __shfl_xor_sync(F, a5, 8);
        a6  += __shfl_xor_sync(F, a6, 8);
        a7  += __shfl_xor_sync(F, a7, 8);
    }
    {   // m = 16
        float t = __shfl_xor_sync(F, sP, 16);
        d4s = (lane & 16) ? (t - sP) : (sP - t);
        d0  += __shfl_xor_sync(F, d0, 16);
        d1s += __shfl_xor_sync(F, d1s, 16);
        d2s += __shfl_xor_sync(F, d2s, 16);
        d3s += __shfl_xor_sync(F, d3s, 16);
        a5  += __shfl_xor_sync(F, a5, 16);
        a6  += __shfl_xor_sync(F, a6, 16);
        a7  += __shfl_xor_sync(F, a7, 16);
    }
    // wire w reads lane bit (4-w): out = d4,d3,d2,d1,d0, a5,a6,a7
    if (lane == 0) {
        float4* o = (float4*)(out + (size_t)gw * 8);
        o[0] = make_float4(d4s, d3s, d2s, d1s);
        o[1] = make_float4(d0, a5, a6, a7);
    }
}

extern "C" void kernel_launch(void* const* d_in, const int* in_sizes, int n_in,
                              void* d_out, int out_size) {
    const float* x    = (const float*)d_in[0];
    const float* ry1  = (const float*)d_in[1];
    const float* crz1 = (const float*)d_in[2];
    const float* ry2  = (const float*)d_in[3];
    const float* crz2 = (const float*)d_in[4];
    float* out = (float*)d_out;

    int nsamp = in_sizes[0] / 8;  // 16384

    vqc_setup<<<1, 256>>>(ry1, crz1, ry2, crz2);

    int blocks = (nsamp + 7) / 8;  // 8 warps (256 threads) per block
    vqc_main<<<blocks, 256>>>(x, out, nsamp);
}